// round 11
// baseline (speedup 1.0000x reference)
#include <cuda_runtime.h>
#include <cstdint>

#define TSTEPS 512
#define BATCH  64
#define HB     32          // half-batch stream size
#define IDIM   256
#define HDIM   2048
#define NMT    32          // h tiles (2048/64)
#define NKG    9           // 8 K-slices of W_hat + 1 for W_in
#define NCTA   (NMT*NKG)   // 288 CTAs, 2 per SM co-resident (<= 296)
#define KSL    256
#define NT     64          // h per CTA tile
#define APAD   260
#define NTHR   128
#define BH     (BATCH*HDIM)
#define HBH    (HB*HDIM)
// SMEM: Wp (permuted weights, 16 p * 2 wc * 4 ni * 32 lane * 4 f) + A buffer
#define WP_FLOATS (16*2*4*32*4)            // 16384 (64 KB)
#define SMEM_BYTES ((WP_FLOATS + HB*APAD)*4)   // 98,816 B -> 2 CTAs/SM

__device__ float    g_state[3][BH];            // triple-buffered state [b][h]
__device__ float    g_part[2][3][NKG][HBH];    // [half][buf(t%3)][kg][b_local*HDIM+h]
__device__ unsigned g_pflag[2][NCTA];          // produce flags per half (monotonic)
__device__ unsigned g_fflag[2][NCTA];          // finalize flags per half (monotonic)

__device__ __forceinline__ void mma_tf32(float* c, const uint32_t* a, const uint32_t* b) {
    asm volatile(
        "mma.sync.aligned.m16n8k8.row.col.f32.tf32.tf32.f32 "
        "{%0,%1,%2,%3}, {%4,%5,%6,%7}, {%8,%9}, {%0,%1,%2,%3};\n"
        : "+f"(c[0]), "+f"(c[1]), "+f"(c[2]), "+f"(c[3])
        : "r"(a[0]), "r"(a[1]), "r"(a[2]), "r"(a[3]), "r"(b[0]), "r"(b[1]));
}
__device__ __forceinline__ uint32_t rna_tf32(float f) {
    uint32_t u; asm("cvt.rna.tf32.f32 %0, %1;" : "=r"(u) : "f"(f)); return u;
}
__device__ __forceinline__ void relstore(unsigned* p, unsigned v) {
    asm volatile("st.release.gpu.global.u32 [%0], %1;" :: "l"(p), "r"(v) : "memory");
}
__device__ __forceinline__ unsigned acqload(const unsigned* p) {
    unsigned v;
    asm volatile("ld.acquire.gpu.global.u32 %0, [%1];" : "=r"(v) : "l"(p) : "memory");
    return v;
}
__device__ __forceinline__ void poll(const unsigned* p, unsigned tgt) {
    while ((int)(acqload(p) - tgt) < 0) { }
}

__global__ void __launch_bounds__(NTHR, 2)
reservoir_kernel(const float* __restrict__ x,     // [T,B,I]
                 const float* __restrict__ s0,    // [B,H]
                 const float* __restrict__ Win,   // [H,I]
                 const float* __restrict__ What,  // [H,H]
                 float* __restrict__ out)         // [T,B,H]
{
    extern __shared__ float smem[];
    float* Wp = smem;                 // permuted weight fragments
    float* As = smem + WP_FLOATS;     // [HB][APAD] A tile (reused per stream)

    const int c   = blockIdx.x;
    const int tid = threadIdx.x;
    const int mt  = c % NMT;
    const int kg  = c / NMT;           // 8 = input projection
    const int warp = tid >> 5, lane = tid & 31;
    const int gid  = lane >> 2, tig = lane & 3;
    const int wm   = (warp & 1) * 16;          // 2 warp-rows over M=32 (batch)
    const int wc   = warp >> 1;                // 2 warp-cols over N=64 (h), 32 each

    const unsigned pb0 = *(volatile unsigned*)&g_pflag[0][c];
    const unsigned pb1 = *(volatile unsigned*)&g_pflag[1][c];
    const unsigned fb0 = *(volatile unsigned*)&g_fflag[0][c];
    const unsigned fb1 = *(volatile unsigned*)&g_fflag[1][c];

    // ---- one-time: weight slice [NT=64 rows x 256 k] -> SMEM, permuted ----
    // Same fragment semantics as R10, with wc range 2: element (r, k=4q+j) ->
    // block = (q>>2)*2 + (r>>5), ni = (r>>3)&3, float_idx =
    // (block*4+ni)*128 + (r&7)*16 + 4*j + (q&3).
    {
        const float* src; int stride;
        if (kg < 8) { src = What + (size_t)mt*NT*HDIM + (size_t)kg*KSL; stride = HDIM; }
        else        { src = Win  + (size_t)mt*NT*IDIM;                  stride = IDIM; }
        for (int i = tid; i < NT*64; i += NTHR) {
            int r = i >> 6, q = i & 63;                // row r, k = 4q..4q+3
            float4 v = *(const float4*)(src + (size_t)r*stride + q*4);
            float* dst = Wp
                + ((((q >> 2)*2 + (r >> 5))*4 + ((r >> 3) & 3))*32 + (r & 7)*4)*4
                + (q & 3);
            dst[0]  = __uint_as_float(rna_tf32(v.x));
            dst[4]  = __uint_as_float(rna_tf32(v.y));
            dst[8]  = __uint_as_float(rna_tf32(v.z));
            dst[12] = __uint_as_float(rna_tf32(v.w));
        }
    }
    // ---- one-time: s0 -> state buffer 2 ----
    if (c < 256) {
        ((float4*)g_state[2])[c*128 + tid] = ((const float4*)s0)[c*128 + tid];
    }
    __syncthreads();
    if (tid == 0) relstore(&g_pflag[0][c], pb0 + 1);
    for (int j = tid; j < NCTA; j += NTHR) poll(&g_pflag[0][j], *(volatile unsigned*)&g_pflag[0][j] > 0 ? (pb0 + 1) : (pb0 + 1));
    __syncthreads();

    // finalize chunk bounds over [HB x NT] block (e = b_local*64 + h_local)
    const int e0 = (kg * (HB*NT)) / NKG;
    const int e1 = ((kg + 1) * (HB*NT)) / NKG;

    for (int t = 0; t < TSTEPS; ++t) {
        const int pbuf = t % 3;

        // ================= produce: stream h = 0, then 1 =================
        for (int h = 0; h < 2; ++h) {
            const unsigned ftgt = (h ? fb1 : fb0) + (unsigned)t;   // t=0 trivially true
            const unsigned ptgt = (h ? pb1 + 1 : pb0 + 2) + (unsigned)t;

            // wait on ALL finalizers of this half from step t-1
            if (kg < 8) {
                for (int j = tid; j < NCTA; j += NTHR) poll(&g_fflag[h][j], ftgt);
            }
            __syncthreads();

            // ---- A tile: state half-slice (or x_t half) -> regs -> SMEM ----
            const float* src = (kg < 8) ? (g_state[(t+2)%3] + (size_t)h*HB*HDIM + kg*KSL)
                                        : (x + (size_t)t*BATCH*IDIM + (size_t)h*HB*IDIM);
            const int stride = (kg < 8) ? HDIM : IDIM;
            #pragma unroll
            for (int pass = 0; pass < 2; ++pass) {
                float4 v[8];
                #pragma unroll
                for (int p = 0; p < 8; ++p) {
                    int i = tid + (pass*8 + p)*NTHR, r = i >> 6, c4 = i & 63;
                    v[p] = *(const float4*)(src + (size_t)r*stride + c4*4);
                }
                #pragma unroll
                for (int p = 0; p < 8; ++p) {
                    int i = tid + (pass*8 + p)*NTHR, r = i >> 6, c4 = i & 63;
                    uint4 u;
                    u.x = rna_tf32(v[p].x); u.y = rna_tf32(v[p].y);
                    u.z = rna_tf32(v[p].z); u.w = rna_tf32(v[p].w);
                    *(uint4*)(As + r*APAD + c4*4) = u;
                }
            }
            __syncthreads();

            // ---- MMA: D[32,64] = As[32,256] * Wp^T ----
            float acc[4][4];
            #pragma unroll
            for (int ni = 0; ni < 4; ++ni)
                #pragma unroll
                for (int q = 0; q < 4; ++q) acc[ni][q] = 0.f;

            #pragma unroll 4
            for (int p = 0; p < 16; ++p) {
                uint4 b4[4];
                #pragma unroll
                for (int ni = 0; ni < 4; ++ni)
                    b4[ni] = *(const uint4*)(Wp + (((p*2 + wc)*4 + ni)*32 + lane)*4);

                const float* ap = As + (wm + gid)*APAD + p*16 + tig;
                uint32_t a0[4], a1[4];
                a0[0] = __float_as_uint(ap[0]);
                a0[1] = __float_as_uint(ap[8*APAD]);
                a0[2] = __float_as_uint(ap[4]);
                a0[3] = __float_as_uint(ap[8*APAD + 4]);
                a1[0] = __float_as_uint(ap[8]);
                a1[1] = __float_as_uint(ap[8*APAD + 8]);
                a1[2] = __float_as_uint(ap[12]);
                a1[3] = __float_as_uint(ap[8*APAD + 12]);

                #pragma unroll
                for (int ni = 0; ni < 4; ++ni) {
                    uint32_t b0[2] = { b4[ni].x, b4[ni].y };
                    mma_tf32(acc[ni], a0, b0);
                }
                #pragma unroll
                for (int ni = 0; ni < 4; ++ni) {
                    uint32_t b1[2] = { b4[ni].z, b4[ni].w };
                    mma_tf32(acc[ni], a1, b1);
                }
            }
            __syncthreads();   // done reading As before next stream overwrites

            // ---- partial store [b_local][h] ----
            {
                float* dst = &g_part[h][pbuf][kg][0] + mt*NT;
                #pragma unroll
                for (int ni = 0; ni < 4; ++ni) {
                    const int row = wm + gid;
                    const int col = wc*32 + ni*8 + tig*2;
                    *(float2*)(dst + (size_t)row*HDIM + col) =
                        make_float2(acc[ni][0], acc[ni][1]);
                    *(float2*)(dst + (size_t)(row+8)*HDIM + col) =
                        make_float2(acc[ni][2], acc[ni][3]);
                }
            }
            __syncthreads();
            if (tid == 0) relstore(&g_pflag[h][c], ptgt);
        }

        // ================= finalize: stream h = 0, then 1 =================
        for (int h = 0; h < 2; ++h) {
            const unsigned ptgt = (h ? pb1 + 1 : pb0 + 2) + (unsigned)t;
            // wait on ALL producers of this half from step t
            for (int j = tid; j < NCTA; j += NTHR) poll(&g_pflag[h][j], ptgt);
            __syncthreads();

            {
                const float* P  = &g_part[h][pbuf][0][0];
                const float* sp = g_state[(t+2)%3];
                float*       sn = g_state[t%3];
                float*       op = out + (size_t)t*BH;

                int e = e0 + tid;
                if (e < e1) {
                    const int bl = e >> 6;
                    const int off = bl*HDIM + mt*NT + (e & 63);
                    float s = P[off];
                    #pragma unroll
                    for (int k2 = 1; k2 < NKG; ++k2) s += P[(size_t)k2*HBH + off];
                    const int so = (h*HB + bl)*HDIM + mt*NT + (e & 63);
                    const float ns = 0.5f*(sp[so] + tanhf(s));
                    sn[so] = ns;
                    op[so] = ns;
                }
                e += NTHR;
                if (e < e1) {
                    const int bl = e >> 6;
                    const int off = bl*HDIM + mt*NT + (e & 63);
                    float s = P[off];
                    #pragma unroll
                    for (int k2 = 1; k2 < NKG; ++k2) s += P[(size_t)k2*HBH + off];
                    const int so = (h*HB + bl)*HDIM + mt*NT + (e & 63);
                    const float ns = 0.5f*(sp[so] + tanhf(s));
                    sn[so] = ns;
                    op[so] = ns;
                }
            }
            __syncthreads();
            if (tid == 0) relstore(&g_fflag[h][c], (h ? fb1 : fb0) + 1 + (unsigned)t);
        }
    }
}

extern "C" void kernel_launch(void* const* d_in, const int* in_sizes, int n_in,
                              void* d_out, int out_size)
{
    (void)in_sizes; (void)n_in; (void)out_size;
    const float* x    = (const float*)d_in[0];
    const float* s0   = (const float*)d_in[1];
    const float* Win  = (const float*)d_in[2];
    const float* What = (const float*)d_in[3];

    cudaFuncSetAttribute(reservoir_kernel,
                         cudaFuncAttributeMaxDynamicSharedMemorySize, SMEM_BYTES);
    reservoir_kernel<<<NCTA, NTHR, SMEM_BYTES>>>(x, s0, Win, What, (float*)d_out);
}

// round 12
// speedup vs baseline: 1.6443x; 1.6443x over previous
#include <cuda_runtime.h>
#include <cstdint>

#define TSTEPS 512
#define BATCH  64
#define HB     32          // half-batch stream size
#define IDIM   256
#define HDIM   2048
#define NMT    16          // h tiles (2048/128)
#define NKG    9           // 8 K-slices of W_hat + 1 for W_in
#define NCTA   (NMT*NKG)   // 144 CTAs co-resident
#define KSL    256
#define NT     128         // h per CTA tile
#define APAD   260
#define NTHR   256
#define BH     (BATCH*HDIM)
#define HBH    (HB*HDIM)
// SMEM: Wp (permuted weights) + A buffer + x prefetch buffer (kg==8 only)
#define WP_FLOATS (16*4*4*32*4)            // 32768
#define XB_FLOATS (HB*IDIM)                // 8192
#define SMEM_BYTES ((WP_FLOATS + HB*APAD + XB_FLOATS)*4)   // 197,120 B

__device__ float    g_state[3][BH];            // triple-buffered state [b][h]
__device__ float    g_part[2][3][NKG][HBH];    // [half][buf(t%3)][kg][b_local*HDIM+h]
__device__ unsigned g_pflag[2][NCTA];          // produce flags per half (monotonic)
__device__ unsigned g_fflag[2][NCTA];          // finalize flags per half (monotonic)

__device__ __forceinline__ void mma_tf32(float* c, const uint32_t* a, const uint32_t* b) {
    asm volatile(
        "mma.sync.aligned.m16n8k8.row.col.f32.tf32.tf32.f32 "
        "{%0,%1,%2,%3}, {%4,%5,%6,%7}, {%8,%9}, {%0,%1,%2,%3};\n"
        : "+f"(c[0]), "+f"(c[1]), "+f"(c[2]), "+f"(c[3])
        : "r"(a[0]), "r"(a[1]), "r"(a[2]), "r"(a[3]), "r"(b[0]), "r"(b[1]));
}
__device__ __forceinline__ uint32_t rna_tf32(float f) {
    uint32_t u; asm("cvt.rna.tf32.f32 %0, %1;" : "=r"(u) : "f"(f)); return u;
}
__device__ __forceinline__ void relstore(unsigned* p, unsigned v) {
    asm volatile("st.release.gpu.global.u32 [%0], %1;" :: "l"(p), "r"(v) : "memory");
}
__device__ __forceinline__ unsigned acqload(const unsigned* p) {
    unsigned v;
    asm volatile("ld.acquire.gpu.global.u32 %0, [%1];" : "=r"(v) : "l"(p) : "memory");
    return v;
}
__device__ __forceinline__ void poll(const unsigned* p, unsigned tgt) {
    while ((int)(acqload(p) - tgt) < 0) { }
}
__device__ __forceinline__ uint32_t smem_u32(const void* p) {
    uint32_t a;
    asm("{ .reg .u64 t; cvta.to.shared.u64 t, %1; cvt.u32.u64 %0, t; }" : "=r"(a) : "l"(p));
    return a;
}
__device__ __forceinline__ void cp_async16(uint32_t dst, const void* src) {
    asm volatile("cp.async.ca.shared.global [%0], [%1], 16;" :: "r"(dst), "l"(src) : "memory");
}
__device__ __forceinline__ void cp_commit() {
    asm volatile("cp.async.commit_group;" ::: "memory");
}
__device__ __forceinline__ void cp_wait0() {
    asm volatile("cp.async.wait_group 0;" ::: "memory");
}

__global__ void __launch_bounds__(NTHR, 1)
reservoir_kernel(const float* __restrict__ x,     // [T,B,I]
                 const float* __restrict__ s0,    // [B,H]
                 const float* __restrict__ Win,   // [H,I]
                 const float* __restrict__ What,  // [H,H]
                 float* __restrict__ out)         // [T,B,H]
{
    extern __shared__ float smem[];
    float* Wp = smem;                            // permuted weight fragments
    float* As = smem + WP_FLOATS;                // [HB][APAD] A tile
    float* Xb = smem + WP_FLOATS + HB*APAD;      // [HB][IDIM] x prefetch (kg==8)
    const uint32_t xb_addr = smem_u32(Xb);

    const int c   = blockIdx.x;
    const int tid = threadIdx.x;
    const int mt  = c % NMT;
    const int kg  = c / NMT;           // 8 = input projection
    const int warp = tid >> 5, lane = tid & 31;
    const int gid  = lane >> 2, tig = lane & 3;
    const int wm   = (warp & 1) * 16;          // 2 warp-rows over M=32 (batch)
    const int wc   = warp >> 1;                // 4 warp-cols over N=128 (h), 32 each

    const unsigned pb0 = *(volatile unsigned*)&g_pflag[0][c];
    const unsigned pb1 = *(volatile unsigned*)&g_pflag[1][c];
    const unsigned fb0 = *(volatile unsigned*)&g_fflag[0][c];
    const unsigned fb1 = *(volatile unsigned*)&g_fflag[1][c];

    // ---- one-time: weight slice -> SMEM in mma-fragment-permuted order ----
    {
        const float* src; int stride;
        if (kg < 8) { src = What + (size_t)mt*NT*HDIM + (size_t)kg*KSL; stride = HDIM; }
        else        { src = Win  + (size_t)mt*NT*IDIM;                  stride = IDIM; }
        for (int i = tid; i < NT*64; i += NTHR) {
            int r = i >> 6, q = i & 63;                // row r, k = 4q..4q+3
            float4 v = *(const float4*)(src + (size_t)r*stride + q*4);
            float* dst = Wp
                + ((((q >> 2)*4 + (r >> 5))*4 + ((r >> 3) & 3))*32 + (r & 7)*4)*4
                + (q & 3);
            dst[0]  = __uint_as_float(rna_tf32(v.x));
            dst[4]  = __uint_as_float(rna_tf32(v.y));
            dst[8]  = __uint_as_float(rna_tf32(v.z));
            dst[12] = __uint_as_float(rna_tf32(v.w));
        }
    }
    // ---- one-time: s0 -> state buffer 2 ----
    if (c < 128) {
        ((float4*)g_state[2])[c*256 + tid] = ((const float4*)s0)[c*256 + tid];
    }
    __syncthreads();
    if (tid == 0) relstore(&g_pflag[0][c], pb0 + 1);
    if (tid < NCTA) poll(&g_pflag[0][tid], pb0 + 1);
    __syncthreads();

    // ---- prime x prefetch: x(0, h0) -> Xb ----
    if (kg == 8) {
        #pragma unroll
        for (int p = 0; p < 8; ++p) {
            int i = tid + p*NTHR, r = i >> 6, c4 = i & 63;
            cp_async16(xb_addr + (uint32_t)(r*IDIM + c4*4)*4, x + (size_t)r*IDIM + c4*4);
        }
        cp_commit();
    }

    // finalize chunk bounds over [HB x NT] block (e = b_local*128 + h_local)
    const int e0 = (kg * (HB*NT)) / NKG;
    const int e1 = ((kg + 1) * (HB*NT)) / NKG;

    for (int t = 0; t < TSTEPS; ++t) {
        const int pbuf = t % 3;

        // ================= produce: stream h = 0, then 1 =================
        for (int h = 0; h < 2; ++h) {
            const unsigned ftgt = (h ? fb1 : fb0) + (unsigned)t;   // t=0 trivially true
            const unsigned ptgt = (h ? pb1 + 1 : pb0 + 2) + (unsigned)t;

            // wait on ALL finalizers of this half from step t-1
            if (kg < 8 && tid < NCTA) poll(&g_fflag[h][tid], ftgt);
            __syncthreads();

            if (kg < 8) {
                // ---- A tile: state half-slice -> regs -> SMEM (tf32 RNA) ----
                const float* src = g_state[(t+2)%3] + (size_t)h*HB*HDIM + kg*KSL;
                float4 v[8];
                #pragma unroll
                for (int p = 0; p < 8; ++p) {
                    int i = tid + p*NTHR, r = i >> 6, c4 = i & 63;
                    v[p] = *(const float4*)(src + (size_t)r*HDIM + c4*4);
                }
                #pragma unroll
                for (int p = 0; p < 8; ++p) {
                    int i = tid + p*NTHR, r = i >> 6, c4 = i & 63;
                    uint4 u;
                    u.x = rna_tf32(v[p].x); u.y = rna_tf32(v[p].y);
                    u.z = rna_tf32(v[p].z); u.w = rna_tf32(v[p].w);
                    *(uint4*)(As + r*APAD + c4*4) = u;
                }
                __syncthreads();
            } else {
                // ---- A tile: prefetched x tile in Xb -> As (tf32 RNA) ----
                cp_wait0();
                __syncthreads();               // prefetched data visible to all
                #pragma unroll
                for (int p = 0; p < 8; ++p) {
                    int i = tid + p*NTHR, r = i >> 6, c4 = i & 63;
                    float4 v = *(const float4*)(Xb + r*IDIM + c4*4);
                    uint4 u;
                    u.x = rna_tf32(v.x); u.y = rna_tf32(v.y);
                    u.z = rna_tf32(v.z); u.w = rna_tf32(v.w);
                    *(uint4*)(As + r*APAD + c4*4) = u;
                }
                __syncthreads();               // staging reads of Xb done
                // issue next prefetch (overlaps with MMA below)
                {
                    const int nt_ = (h == 0) ? t : ((t + 1 < TSTEPS) ? t + 1 : t);
                    const int nh  = 1 - h;
                    const float* nsrc = x + (size_t)nt_*BATCH*IDIM + (size_t)nh*HB*IDIM;
                    #pragma unroll
                    for (int p = 0; p < 8; ++p) {
                        int i = tid + p*NTHR, r = i >> 6, c4 = i & 63;
                        cp_async16(xb_addr + (uint32_t)(r*IDIM + c4*4)*4,
                                   nsrc + (size_t)r*IDIM + c4*4);
                    }
                    cp_commit();
                }
            }

            // ---- MMA: D[32,128] = As[32,256] * Wp^T ----
            float acc[4][4];
            #pragma unroll
            for (int ni = 0; ni < 4; ++ni)
                #pragma unroll
                for (int q = 0; q < 4; ++q) acc[ni][q] = 0.f;

            #pragma unroll 4
            for (int p = 0; p < 16; ++p) {
                uint4 b4[4];
                #pragma unroll
                for (int ni = 0; ni < 4; ++ni)
                    b4[ni] = *(const uint4*)(Wp + (((p*4 + wc)*4 + ni)*32 + lane)*4);

                const float* ap = As + (wm + gid)*APAD + p*16 + tig;
                uint32_t a0[4], a1[4];
                a0[0] = __float_as_uint(ap[0]);
                a0[1] = __float_as_uint(ap[8*APAD]);
                a0[2] = __float_as_uint(ap[4]);
                a0[3] = __float_as_uint(ap[8*APAD + 4]);
                a1[0] = __float_as_uint(ap[8]);
                a1[1] = __float_as_uint(ap[8*APAD + 8]);
                a1[2] = __float_as_uint(ap[12]);
                a1[3] = __float_as_uint(ap[8*APAD + 12]);

                #pragma unroll
                for (int ni = 0; ni < 4; ++ni) {
                    uint32_t b0[2] = { b4[ni].x, b4[ni].y };
                    mma_tf32(acc[ni], a0, b0);
                }
                #pragma unroll
                for (int ni = 0; ni < 4; ++ni) {
                    uint32_t b1[2] = { b4[ni].z, b4[ni].w };
                    mma_tf32(acc[ni], a1, b1);
                }
            }

            // ---- partial store [b_local][h] ----
            {
                float* dst = &g_part[h][pbuf][kg][0] + mt*NT;
                #pragma unroll
                for (int ni = 0; ni < 4; ++ni) {
                    const int row = wm + gid;
                    const int col = wc*32 + ni*8 + tig*2;
                    *(float2*)(dst + (size_t)row*HDIM + col) =
                        make_float2(acc[ni][0], acc[ni][1]);
                    *(float2*)(dst + (size_t)(row+8)*HDIM + col) =
                        make_float2(acc[ni][2], acc[ni][3]);
                }
            }
            __syncthreads();   // all partial stores done; also guards As reuse
            if (tid == 0) relstore(&g_pflag[h][c], ptgt);
        }

        // ================= finalize: stream h = 0, then 1 =================
        for (int h = 0; h < 2; ++h) {
            const unsigned ptgt = (h ? pb1 + 1 : pb0 + 2) + (unsigned)t;
            // wait on ALL producers of this half from step t
            if (tid < NCTA) poll(&g_pflag[h][tid], ptgt);
            __syncthreads();

            {
                const float* P  = &g_part[h][pbuf][0][0];
                const float* sp = g_state[(t+2)%3];
                float*       sn = g_state[t%3];
                float*       op = out + (size_t)t*BH;

                const int ea = e0 + tid;
                const int eb = ea + NTHR;
                const bool va = ea < e1;
                const bool vb = eb < e1;
                int offa = 0, soa = 0, offb = 0, sob = 0;
                if (va) {
                    const int bl = ea >> 7;
                    offa = bl*HDIM + mt*NT + (ea & 127);
                    soa  = (h*HB + bl)*HDIM + mt*NT + (ea & 127);
                }
                if (vb) {
                    const int bl = eb >> 7;
                    offb = bl*HDIM + mt*NT + (eb & 127);
                    sob  = (h*HB + bl)*HDIM + mt*NT + (eb & 127);
                }
                // batched loads (full MLP)
                float la[NKG], lb[NKG], spa = 0.f, spb = 0.f;
                if (va) {
                    #pragma unroll
                    for (int k2 = 0; k2 < NKG; ++k2) la[k2] = P[(size_t)k2*HBH + offa];
                    spa = sp[soa];
                }
                if (vb) {
                    #pragma unroll
                    for (int k2 = 0; k2 < NKG; ++k2) lb[k2] = P[(size_t)k2*HBH + offb];
                    spb = sp[sob];
                }
                if (va) {
                    float s = la[0];
                    #pragma unroll
                    for (int k2 = 1; k2 < NKG; ++k2) s += la[k2];
                    const float ns = 0.5f*(spa + tanhf(s));
                    sn[soa] = ns;
                    op[soa] = ns;
                }
                if (vb) {
                    float s = lb[0];
                    #pragma unroll
                    for (int k2 = 1; k2 < NKG; ++k2) s += lb[k2];
                    const float ns = 0.5f*(spb + tanhf(s));
                    sn[sob] = ns;
                    op[sob] = ns;
                }
            }
            __syncthreads();
            if (tid == 0) relstore(&g_fflag[h][c], (h ? fb1 : fb0) + 1 + (unsigned)t);
        }
    }
}

extern "C" void kernel_launch(void* const* d_in, const int* in_sizes, int n_in,
                              void* d_out, int out_size)
{
    (void)in_sizes; (void)n_in; (void)out_size;
    const float* x    = (const float*)d_in[0];
    const float* s0   = (const float*)d_in[1];
    const float* Win  = (const float*)d_in[2];
    const float* What = (const float*)d_in[3];

    cudaFuncSetAttribute(reservoir_kernel,
                         cudaFuncAttributeMaxDynamicSharedMemorySize, SMEM_BYTES);
    reservoir_kernel<<<NCTA, NTHR, SMEM_BYTES>>>(x, s0, Win, What, (float*)d_out);
}